// round 4
// baseline (speedup 1.0000x reference)
#include <cuda_runtime.h>
#include <cuda_bf16.h>
#include <mma.h>
#include <cstdint>

using namespace nvcuda;

#define B_    2048
#define D_    512
#define V_    100000
#define K_    32
#define BM    64
#define BN    512
#define BK    32
#define TILES_V 196                 // ceil(100000/512)
#define VP    (TILES_V * BN)        // 100352 (padded V)
#define TCAND 16                    // candidates kept per (row, col-tile)
#define CPR   (TILES_V * TCAND)     // 3136 candidates per row
#define RESC  48                    // candidates rescored in fp32 per row
#define NEGF  (-1e30f)

// ---- device scratch (no allocations allowed) ----
__device__ __nv_bfloat16 g_Wb[(size_t)VP * D_];   // bf16 weight, padded rows zeroed
__device__ __nv_bfloat16 g_xb[(size_t)B_ * D_];   // bf16 x
__device__ float g_cval[(size_t)B_ * CPR];
__device__ int   g_cidx[(size_t)B_ * CPR];

// ---------------- conversion kernels ----------------
__global__ void cvtW(const float4* __restrict__ W4) {
    size_t i = (size_t)blockIdx.x * blockDim.x + threadIdx.x;
    size_t tot = (size_t)VP * D_ / 4;
    if (i >= tot) return;
    float4 v;
    if (i < (size_t)V_ * D_ / 4) v = W4[i];
    else v = make_float4(0.f, 0.f, 0.f, 0.f);
    __nv_bfloat162 lo = __floats2bfloat162_rn(v.x, v.y);
    __nv_bfloat162 hi = __floats2bfloat162_rn(v.z, v.w);
    ((__nv_bfloat162*)g_Wb)[2 * i]     = lo;
    ((__nv_bfloat162*)g_Wb)[2 * i + 1] = hi;
}

__global__ void cvtX(const float4* __restrict__ X4) {
    size_t i = (size_t)blockIdx.x * blockDim.x + threadIdx.x;
    size_t tot = (size_t)B_ * D_ / 4;
    if (i >= tot) return;
    float4 v = X4[i];
    __nv_bfloat162 lo = __floats2bfloat162_rn(v.x, v.y);
    __nv_bfloat162 hi = __floats2bfloat162_rn(v.z, v.w);
    ((__nv_bfloat162*)g_xb)[2 * i]     = lo;
    ((__nv_bfloat162*)g_xb)[2 * i + 1] = hi;
}

// ---------------- GEMM (wmma bf16) + fused per-tile top-16 ----------------
extern __shared__ unsigned char smem_raw[];

__global__ void __launch_bounds__(512)
gemm_sel(const float* __restrict__ bias, const int* __restrict__ mask) {
    __nv_bfloat16* sA = (__nv_bfloat16*)smem_raw;             // 64 x 32
    __nv_bfloat16* sB = (__nv_bfloat16*)(smem_raw + 4096);    // 512 x 32
    float*         sC = (float*)smem_raw;                     // 64 x 512 (reuse after GEMM)

    const int rt = blockIdx.x;        // row tile  (0..31)
    const int ct = blockIdx.y;        // col tile  (0..195)
    const int rowBase = rt * BM;
    const int vBase   = ct * BN;
    const int tid  = threadIdx.x;
    const int wid  = tid >> 5;
    const int lane = tid & 31;
    const int wr = wid >> 2;          // warp row group (0..3), 16 rows each
    const int wc = wid & 3;           // warp col group (0..3), 128 cols each

    wmma::fragment<wmma::accumulator, 16, 16, 16, float> acc[8];
#pragma unroll
    for (int j = 0; j < 8; j++) wmma::fill_fragment(acc[j], 0.0f);

    for (int kt = 0; kt < D_ / BK; kt++) {
        const int k0 = kt * BK;
        if (tid < 256) {                       // A tile: 256 int4
            int r = tid >> 2, c = tid & 3;
            *(int4*)(sA + r * BK + c * 8) =
                *(const int4*)(g_xb + (size_t)(rowBase + r) * D_ + k0 + c * 8);
        }
#pragma unroll
        for (int i = 0; i < 4; i++) {          // B tile: 2048 int4
            int lin = tid + i * 512;
            int r = lin >> 2, c = lin & 3;
            *(int4*)(sB + r * BK + c * 8) =
                *(const int4*)(g_Wb + (size_t)(vBase + r) * D_ + k0 + c * 8);
        }
        __syncthreads();
#pragma unroll
        for (int kk = 0; kk < BK; kk += 16) {
            wmma::fragment<wmma::matrix_a, 16, 16, 16, __nv_bfloat16, wmma::row_major> af;
            wmma::load_matrix_sync(af, sA + (wr * 16) * BK + kk, BK);
#pragma unroll
            for (int j = 0; j < 8; j++) {
                wmma::fragment<wmma::matrix_b, 16, 16, 16, __nv_bfloat16, wmma::col_major> bf;
                wmma::load_matrix_sync(bf, sB + (wc * 128 + j * 16) * BK + kk, BK);
                wmma::mma_sync(acc[j], af, bf, acc[j]);
            }
        }
        __syncthreads();
    }

    // dump accumulators to shared (reuses operand space)
#pragma unroll
    for (int j = 0; j < 8; j++)
        wmma::store_matrix_sync(sC + (wr * 16) * BN + wc * 128 + j * 16, acc[j], BN,
                                wmma::mem_row_major);
    __syncthreads();

    // per-row top-16 over this 512-col tile (one warp -> 4 rows)
    for (int q = 0; q < 4; q++) {
        const int r  = wid * 4 + q;
        const int gr = rowBase + r;
        float lv[16]; int lc[16];
#pragma unroll
        for (int s = 0; s < 16; s++) {
            int c  = lane + s * 32;
            int gc = vBase + c;
            float v = NEGF;
            if (gc < V_ && mask[(size_t)gr * V_ + gc] != 0) v = sC[r * BN + c] + bias[gc];
            lv[s] = v; lc[s] = gc;
        }
        const size_t obase = (size_t)gr * CPR + (size_t)ct * TCAND;
        for (int t = 0; t < TCAND; t++) {
            float bmv = lv[0]; int bmc = lc[0];
#pragma unroll
            for (int s = 1; s < 16; s++)
                if (lv[s] > bmv || (lv[s] == bmv && lc[s] < bmc)) { bmv = lv[s]; bmc = lc[s]; }
            float v = bmv; int c = bmc;
#pragma unroll
            for (int off = 16; off; off >>= 1) {
                float ov = __shfl_xor_sync(0xffffffffu, v, off);
                int   oc = __shfl_xor_sync(0xffffffffu, c, off);
                if (ov > v || (ov == v && oc < c)) { v = ov; c = oc; }
            }
            if (c == bmc) {   // winning lane invalidates its slot (cols are unique)
#pragma unroll
                for (int s = 0; s < 16; s++)
                    if (lc[s] == c) lv[s] = -3.4e38f;
            }
            if (lane == 0) { g_cval[obase + t] = v; g_cidx[obase + t] = c; }
        }
    }
}

// ---------------- finalize: per-row top-48 approx -> sequential-FMA fp32 rescore -> exact top-32 ----------------
__global__ void __launch_bounds__(256)
finalize(const float* __restrict__ x, const float* __restrict__ W,
         const float* __restrict__ bias, float* __restrict__ out, int out_size) {
    __shared__ float sv[CPR];
    __shared__ int   si[CPR];
    __shared__ float sx[D_];
    __shared__ float wbest[8];
    __shared__ int   wpos[8];
    __shared__ float cv[RESC];
    __shared__ int   ci[RESC];
    __shared__ float rv[RESC];

    const int row = blockIdx.x;
    const int tid = threadIdx.x, lane = tid & 31, wid = tid >> 5;

    for (int i = tid; i < CPR; i += 256) {
        sv[i] = g_cval[(size_t)row * CPR + i];
        si[i] = g_cidx[(size_t)row * CPR + i];
    }
    for (int i = tid; i < D_; i += 256) sx[i] = x[(size_t)row * D_ + i];
    __syncthreads();

    // extract top-48 approximate candidates
    for (int t = 0; t < RESC; t++) {
        float bv = -3.4e38f; int bp = 0x7fffffff;
        for (int i = tid; i < CPR; i += 256) {
            float v = sv[i];
            if (v > bv || (v == bv && i < bp)) { bv = v; bp = i; }
        }
#pragma unroll
        for (int off = 16; off; off >>= 1) {
            float ov = __shfl_xor_sync(0xffffffffu, bv, off);
            int   op = __shfl_xor_sync(0xffffffffu, bp, off);
            if (ov > bv || (ov == bv && op < bp)) { bv = ov; bp = op; }
        }
        if (lane == 0) { wbest[wid] = bv; wpos[wid] = bp; }
        __syncthreads();
        if (tid == 0) {
            float fv = wbest[0]; int fp = wpos[0];
            for (int w = 1; w < 8; w++)
                if (wbest[w] > fv || (wbest[w] == fv && wpos[w] < fp)) { fv = wbest[w]; fp = wpos[w]; }
            cv[t] = fv; ci[t] = si[fp];
            sv[fp] = -3.4e38f;
        }
        __syncthreads();
    }

    // exact fp32 rescore: ONE THREAD per candidate, strictly sequential FMA over
    // k = 0..511 ascending into a single accumulator — reproduces the per-element
    // summation order of the reference GEMM (Eigen gebp / cublas SGEMM k-loop),
    // so near-tie orderings match the reference bit-for-bit.
    if (tid < RESC) {
        const int t = tid;
        float v = cv[t];
        if (v <= -1e29f) {
            rv[t] = NEGF;                       // masked / padding: reference's -1e30
        } else {
            const int col = ci[t];
            const float4* wrow = (const float4*)(W + (size_t)col * D_);
            float s = 0.f;
#pragma unroll 8
            for (int k4 = 0; k4 < D_ / 4; k4++) {
                float4 w4 = __ldg(&wrow[k4]);
                s = fmaf(sx[k4 * 4 + 0], w4.x, s);
                s = fmaf(sx[k4 * 4 + 1], w4.y, s);
                s = fmaf(sx[k4 * 4 + 2], w4.z, s);
                s = fmaf(sx[k4 * 4 + 3], w4.w, s);
            }
            rv[t] = s + bias[col];
        }
    }
    __syncthreads();

    // exact top-32 with jax tie-break (value desc, index asc)
    if (tid == 0) {
        for (int j = 0; j < K_; j++) {
            float bv = -3.4e38f; int bc = 0x7fffffff; int bt = -1;
            for (int t = 0; t < RESC; t++) {
                float v = rv[t];
                if (v <= -3.3e38f) continue;           // consumed
                int c = ci[t];
                if (bt < 0 || v > bv || (v == bv && c < bc)) { bv = v; bc = c; bt = t; }
            }
            rv[bt] = -3.4e38f;
            out[(size_t)row * K_ + j] = bv;
            if (out_size >= 2 * B_ * K_)
                out[(size_t)B_ * K_ + (size_t)row * K_ + j] = (float)bc;
        }
    }
}

// ---------------- launch ----------------
extern "C" void kernel_launch(void* const* d_in, const int* in_sizes, int n_in,
                              void* d_out, int out_size) {
    const float* x    = (const float*)d_in[0];
    const float* W    = (const float*)d_in[1];
    const float* bias = (const float*)d_in[2];
    const int*   mask = (const int*)d_in[3];
    float* out = (float*)d_out;

    cudaFuncSetAttribute(gemm_sel, cudaFuncAttributeMaxDynamicSharedMemorySize, 131072);

    {
        size_t tot = (size_t)VP * D_ / 4;
        cvtW<<<(unsigned)((tot + 255) / 256), 256>>>((const float4*)W);
    }
    {
        size_t tot = (size_t)B_ * D_ / 4;
        cvtX<<<(unsigned)((tot + 255) / 256), 256>>>((const float4*)x);
    }
    gemm_sel<<<dim3(32, TILES_V), 512, 131072>>>(bias, mask);
    finalize<<<B_, 256>>>(x, W, bias, out, out_size);
}

// round 5
// speedup vs baseline: 1.9950x; 1.9950x over previous
#include <cuda_runtime.h>
#include <cuda_bf16.h>
#include <cstdint>

#define B_    2048
#define D_    512
#define V_    100000
#define K_    32
#define BM    64
#define BN    256
#define BK    64
#define NKT   (D_ / BK)              // 8
#define TILES_V 392                  // 100352 / 256
#define VP    (TILES_V * BN)         // 100352
#define TCAND 6                      // candidates per (row, 256-col tile)
#define CPR   (TILES_V * TCAND)      // 2352
#define RESC  40                     // approx top-RESC captured for rescore
#define CAP   128
#define NEGF  (-1e30f)
#define LDA   72                     // 64 + 8 bf16 pad (144B rows, conflict-free)
#define LDB   72
#define LDC   260

// ---- device scratch (no allocations allowed) ----
__device__ __nv_bfloat16 g_Wb[(size_t)VP * D_];
__device__ __nv_bfloat16 g_xb[(size_t)B_ * D_];
__device__ float g_cval[(size_t)B_ * CPR];
__device__ int   g_cidx[(size_t)B_ * CPR];

// ---------------- conversion kernels ----------------
__global__ void cvtW(const float4* __restrict__ W4) {
    size_t i = (size_t)blockIdx.x * blockDim.x + threadIdx.x;
    size_t tot = (size_t)VP * D_ / 4;
    if (i >= tot) return;
    float4 v;
    if (i < (size_t)V_ * D_ / 4) v = W4[i];
    else v = make_float4(0.f, 0.f, 0.f, 0.f);
    __nv_bfloat162 lo = __floats2bfloat162_rn(v.x, v.y);
    __nv_bfloat162 hi = __floats2bfloat162_rn(v.z, v.w);
    ((__nv_bfloat162*)g_Wb)[2 * i]     = lo;
    ((__nv_bfloat162*)g_Wb)[2 * i + 1] = hi;
}

__global__ void cvtX(const float4* __restrict__ X4) {
    size_t i = (size_t)blockIdx.x * blockDim.x + threadIdx.x;
    size_t tot = (size_t)B_ * D_ / 4;
    if (i >= tot) return;
    float4 v = X4[i];
    __nv_bfloat162 lo = __floats2bfloat162_rn(v.x, v.y);
    __nv_bfloat162 hi = __floats2bfloat162_rn(v.z, v.w);
    ((__nv_bfloat162*)g_xb)[2 * i]     = lo;
    ((__nv_bfloat162*)g_xb)[2 * i + 1] = hi;
}

// ---------------- GEMM (PTX mma bf16, cp.async double-buffer) + fused top-6/tile ----------------
extern __shared__ unsigned char smem_raw[];

__device__ __forceinline__ unsigned sptr(const void* p) {
    return (unsigned)__cvta_generic_to_shared(p);
}

__global__ void __launch_bounds__(256)
gemm_sel(const float* __restrict__ bias, const int* __restrict__ mask) {
    const int tid  = threadIdx.x;
    const int lane = tid & 31, wid = tid >> 5;
    const int wm = wid >> 2, wn = wid & 3;      // 2 (m) x 4 (n) warp grid
    const int g = lane >> 2, tig = lane & 3;    // mma group / thread-in-group
    const int rt = blockIdx.x, ct = blockIdx.y;
    const int rowBase = rt * BM, vBase = ct * BN;

    __nv_bfloat16* sA0 = (__nv_bfloat16*)smem_raw;                      //  9216 B
    __nv_bfloat16* sB0 = (__nv_bfloat16*)(smem_raw + 9216);             // 36864 B
    __nv_bfloat16* sA1 = (__nv_bfloat16*)(smem_raw + 46080);
    __nv_bfloat16* sB1 = (__nv_bfloat16*)(smem_raw + 46080 + 9216);
    float* sC = (float*)smem_raw;                                       // 64*260*4 (reuse)

    float acc[2][8][4];
#pragma unroll
    for (int mt = 0; mt < 2; mt++)
#pragma unroll
        for (int j = 0; j < 8; j++)
#pragma unroll
            for (int e = 0; e < 4; e++) acc[mt][j][e] = 0.f;

#define LOAD_TILE(sa, sb, kt)                                                        \
    do {                                                                             \
        const int k0 = (kt) * BK;                                                    \
        _Pragma("unroll")                                                            \
        for (int i = 0; i < 2; i++) {                                                \
            int c = tid + i * 256, r = c >> 3, ch = c & 7;                           \
            unsigned dst = sptr((sa) + r * LDA + ch * 8);                            \
            const void* src = g_xb + (size_t)(rowBase + r) * D_ + k0 + ch * 8;       \
            asm volatile("cp.async.cg.shared.global [%0], [%1], 16;\n"               \
                         :: "r"(dst), "l"(src));                                     \
        }                                                                            \
        _Pragma("unroll")                                                            \
        for (int i = 0; i < 8; i++) {                                                \
            int c = tid + i * 256, r = c >> 3, ch = c & 7;                           \
            unsigned dst = sptr((sb) + r * LDB + ch * 8);                            \
            const void* src = g_Wb + (size_t)(vBase + r) * D_ + k0 + ch * 8;         \
            asm volatile("cp.async.cg.shared.global [%0], [%1], 16;\n"               \
                         :: "r"(dst), "l"(src));                                     \
        }                                                                            \
        asm volatile("cp.async.commit_group;\n");                                    \
    } while (0)

#define COMPUTE_TILE(sa, sb)                                                         \
    do {                                                                             \
        _Pragma("unroll")                                                            \
        for (int ks = 0; ks < 4; ks++) {                                             \
            const int kk = ks * 16;                                                  \
            unsigned a[2][4];                                                        \
            _Pragma("unroll")                                                        \
            for (int mt = 0; mt < 2; mt++) {                                         \
                const __nv_bfloat16* ab = (sa) + (wm * 32 + mt * 16 + g) * LDA       \
                                               + kk + 2 * tig;                       \
                a[mt][0] = *(const unsigned*)(ab);                                   \
                a[mt][1] = *(const unsigned*)(ab + 8 * LDA);                         \
                a[mt][2] = *(const unsigned*)(ab + 8);                               \
                a[mt][3] = *(const unsigned*)(ab + 8 * LDA + 8);                     \
            }                                                                        \
            _Pragma("unroll")                                                        \
            for (int j = 0; j < 8; j++) {                                            \
                const __nv_bfloat16* bb = (sb) + (wn * 64 + j * 8 + g) * LDB         \
                                               + kk + 2 * tig;                       \
                unsigned b0 = *(const unsigned*)(bb);                                \
                unsigned b1 = *(const unsigned*)(bb + 8);                            \
                _Pragma("unroll")                                                    \
                for (int mt = 0; mt < 2; mt++) {                                     \
                    asm volatile(                                                    \
                        "mma.sync.aligned.m16n8k16.row.col.f32.bf16.bf16.f32 "       \
                        "{%0,%1,%2,%3}, {%4,%5,%6,%7}, {%8,%9}, {%0,%1,%2,%3};\n"    \
                        : "+f"(acc[mt][j][0]), "+f"(acc[mt][j][1]),                  \
                          "+f"(acc[mt][j][2]), "+f"(acc[mt][j][3])                   \
                        : "r"(a[mt][0]), "r"(a[mt][1]), "r"(a[mt][2]),               \
                          "r"(a[mt][3]), "r"(b0), "r"(b1));                          \
                }                                                                    \
            }                                                                        \
        }                                                                            \
    } while (0)

    LOAD_TILE(sA0, sB0, 0);
#pragma unroll 2
    for (int kt = 0; kt < NKT; kt++) {
        const bool cur0 = (kt & 1) == 0;
        if (kt + 1 < NKT) {
            if (cur0) LOAD_TILE(sA1, sB1, kt + 1);
            else      LOAD_TILE(sA0, sB0, kt + 1);
            asm volatile("cp.async.wait_group 1;\n");
        } else {
            asm volatile("cp.async.wait_group 0;\n");
        }
        __syncthreads();
        if (cur0) COMPUTE_TILE(sA0, sB0);
        else      COMPUTE_TILE(sA1, sB1);
        __syncthreads();
    }

    // stage C into smem (reuses pipeline buffers; barrier above guarantees safety)
#pragma unroll
    for (int mt = 0; mt < 2; mt++)
#pragma unroll
        for (int j = 0; j < 8; j++) {
            const int r0 = wm * 32 + mt * 16 + g;
            const int c0 = wn * 64 + j * 8 + 2 * tig;
            sC[r0 * LDC + c0]           = acc[mt][j][0];
            sC[r0 * LDC + c0 + 1]       = acc[mt][j][1];
            sC[(r0 + 8) * LDC + c0]     = acc[mt][j][2];
            sC[(r0 + 8) * LDC + c0 + 1] = acc[mt][j][3];
        }
    __syncthreads();

    // per-row top-6 over this 256-col tile (one warp -> 8 rows)
    for (int q = 0; q < 8; q++) {
        const int r  = wid * 8 + q;
        const int gr = rowBase + r;
        float lv[8]; int lc[8];
#pragma unroll
        for (int s = 0; s < 8; s++) {
            const int c  = lane + s * 32;
            const int gc = vBase + c;
            float v = NEGF;
            if (gc < V_ && mask[(size_t)gr * V_ + gc] != 0)
                v = sC[r * LDC + c] + __ldg(&bias[gc]);
            lv[s] = v; lc[s] = gc;
        }
        const size_t obase = (size_t)gr * CPR + (size_t)ct * TCAND;
        for (int t = 0; t < TCAND; t++) {
            float bmv = lv[0]; int bmc = lc[0];
#pragma unroll
            for (int s = 1; s < 8; s++)
                if (lv[s] > bmv || (lv[s] == bmv && lc[s] < bmc)) { bmv = lv[s]; bmc = lc[s]; }
            float v = bmv; int c = bmc;
#pragma unroll
            for (int off = 16; off; off >>= 1) {
                float ov = __shfl_xor_sync(0xffffffffu, v, off);
                int   oc = __shfl_xor_sync(0xffffffffu, c, off);
                if (ov > v || (ov == v && oc < c)) { v = ov; c = oc; }
            }
            if (c == bmc) {
#pragma unroll
                for (int s = 0; s < 8; s++)
                    if (lc[s] == c) lv[s] = -3.4e38f;
            }
            if (lane == 0) { g_cval[obase + t] = v; g_cidx[obase + t] = c; }
        }
    }
}

// ---------------- finalize: histogram threshold-select -> seq-FMA rescore -> exact top-32 ----------------
__device__ __forceinline__ int fbin(float v) {
    float t = (v + 8.0f) * (1024.0f / 24.0f);   // linear bins over [-8, 16]
    int b = (int)t;
    return b < 0 ? 0 : (b > 1023 ? 1023 : b);
}

__global__ void __launch_bounds__(256)
finalize(const float* __restrict__ x, const float* __restrict__ W,
         const float* __restrict__ bias, float* __restrict__ out, int out_size) {
    __shared__ float sv[CPR];
    __shared__ int   si[CPR];
    __shared__ float sx[D_];
    __shared__ int   hist[1024];
    __shared__ float cv[CAP];
    __shared__ int   ci[CAP];
    __shared__ float rv[CAP];
    __shared__ int   s_thr, s_cnt;

    const int row = blockIdx.x;
    const int tid = threadIdx.x, lane = tid & 31, wid = tid >> 5;

    for (int i = tid; i < 1024; i += 256) hist[i] = 0;
    if (tid == 0) s_cnt = 0;
    for (int i = tid; i < D_; i += 256) sx[i] = x[(size_t)row * D_ + i];
    for (int i = tid; i < CPR; i += 256) {
        sv[i] = g_cval[(size_t)row * CPR + i];
        si[i] = g_cidx[(size_t)row * CPR + i];
    }
    __syncthreads();

    for (int i = tid; i < CPR; i += 256) atomicAdd(&hist[fbin(sv[i])], 1);
    __syncthreads();

    // warp 0: find smallest bin thr with count(bin >= thr) >= RESC
    if (wid == 0) {
        const int base = 1023 - 32 * lane;      // lane 0 = topmost 32-bin chunk
        int s = 0;
#pragma unroll
        for (int i = 0; i < 32; i++) s += hist[base - i];
        int pref = s;
#pragma unroll
        for (int off = 1; off < 32; off <<= 1) {
            int o = __shfl_up_sync(0xffffffffu, pref, off);
            if (lane >= off) pref += o;
        }
        unsigned bal = __ballot_sync(0xffffffffu, pref >= RESC);
        int sel = bal ? (__ffs(bal) - 1) : 31;
        if (lane == sel) {
            int thr = 0;
            if (bal) {
                int cum = pref - s;
                for (int i = 0; i < 32; i++) {
                    cum += hist[base - i];
                    if (cum >= RESC) { thr = base - i; break; }
                }
            }
            s_thr = thr;
        }
    }
    __syncthreads();

    const int thr = s_thr;
    for (int i = tid; i < CPR; i += 256) {
        if (fbin(sv[i]) >= thr) {
            int p = atomicAdd(&s_cnt, 1);
            if (p < CAP) { cv[p] = sv[i]; ci[p] = si[i]; }
        }
    }
    __syncthreads();
    const int cnt = min(s_cnt, CAP);

    // exact fp32 rescore: strictly sequential FMA over k ascending (matches reference
    // per-element summation order -> bit-identical near-tie ordering)
    if (tid < cnt) {
        float v = cv[tid];
        if (v <= -1e29f) rv[tid] = NEGF;
        else {
            const int col = ci[tid];
            const float4* wrow = (const float4*)(W + (size_t)col * D_);
            float s = 0.f;
#pragma unroll 8
            for (int k4 = 0; k4 < D_ / 4; k4++) {
                float4 w4 = __ldg(&wrow[k4]);
                s = fmaf(sx[k4 * 4 + 0], w4.x, s);
                s = fmaf(sx[k4 * 4 + 1], w4.y, s);
                s = fmaf(sx[k4 * 4 + 2], w4.z, s);
                s = fmaf(sx[k4 * 4 + 3], w4.w, s);
            }
            rv[tid] = s + bias[col];
        }
    }
    __syncthreads();

    // warp 0: exact top-32, tie-break (value desc, index asc)
    if (wid == 0) {
        for (int j = 0; j < K_; j++) {
            float bv = -3.4e38f; int bc = 0x7fffffff; int bp = -1;
            for (int p = lane; p < cnt; p += 32) {
                float v = rv[p];
                if (v <= -3.3e38f) continue;
                int c = ci[p];
                if (bp < 0 || v > bv || (v == bv && c < bc)) { bv = v; bc = c; bp = p; }
            }
#pragma unroll
            for (int off = 16; off; off >>= 1) {
                float ov = __shfl_xor_sync(0xffffffffu, bv, off);
                int   oc = __shfl_xor_sync(0xffffffffu, bc, off);
                int   op = __shfl_xor_sync(0xffffffffu, bp, off);
                bool take = (op >= 0) && (bp < 0 || ov > bv || (ov == bv && oc < bc));
                if (take) { bv = ov; bc = oc; bp = op; }
            }
            if (lane == 0) {
                out[(size_t)row * K_ + j] = bv;
                if (out_size >= 2 * B_ * K_)
                    out[(size_t)B_ * K_ + (size_t)row * K_ + j] = (float)bc;
                if (bp >= 0) rv[bp] = -3.4e38f;
            }
            __syncwarp();
        }
    }
}

// ---------------- launch ----------------
extern "C" void kernel_launch(void* const* d_in, const int* in_sizes, int n_in,
                              void* d_out, int out_size) {
    const float* x    = (const float*)d_in[0];
    const float* W    = (const float*)d_in[1];
    const float* bias = (const float*)d_in[2];
    const int*   mask = (const int*)d_in[3];
    float* out = (float*)d_out;

    cudaFuncSetAttribute(gemm_sel, cudaFuncAttributeMaxDynamicSharedMemorySize, 92160);

    {
        size_t tot = (size_t)VP * D_ / 4;
        cvtW<<<(unsigned)((tot + 255) / 256), 256>>>((const float4*)W);
    }
    {
        size_t tot = (size_t)B_ * D_ / 4;
        cvtX<<<(unsigned)((tot + 255) / 256), 256>>>((const float4*)x);
    }
    gemm_sel<<<dim3(32, TILES_V), 256, 92160>>>(bias, mask);
    finalize<<<B_, 256>>>(x, W, bias, out, out_size);
}